// round 12
// baseline (speedup 1.0000x reference)
#include <cuda_runtime.h>
#include <cstdint>
#include <cstddef>

#define TT   4096
#define EMBD 100
#define HIDN 512
#define G3   1536

typedef unsigned long long ull;

// ---------------- scratch (no cudaMalloc allowed) ----------------
__device__ float g_x[TT * EMBD];            // embedded inputs
__device__ float g_y0[TT * 1024];           // layer-0 output
__device__ float g_gi0[2 * TT * G3];        // layer-0 input gates
__device__ float g_gi1[2 * TT * G3];        // layer-1 gates, fwd-half + bias
__device__ float g_gi1b[2 * TT * G3];       // layer-1 gates, bwd-half
__device__ int   g_prog[2][16];             // GRU-L0 progress counters

// ---------------- helpers ----------------
__device__ __forceinline__ void cluster_sync_() {
    asm volatile("barrier.cluster.arrive.aligned;" ::: "memory");
    asm volatile("barrier.cluster.wait.aligned;" ::: "memory");
}

__device__ __forceinline__ void bulk_push(unsigned dst, unsigned src,
                                          unsigned mb, unsigned rank,
                                          unsigned bytes) {
    asm volatile(
        "{\n\t.reg .u32 rd, rb;\n\t"
        "mapa.shared::cluster.u32 rd, %0, %3;\n\t"
        "mapa.shared::cluster.u32 rb, %2, %3;\n\t"
        "cp.async.bulk.shared::cluster.shared::cta.mbarrier::complete_tx::bytes "
        "[rd], [%1], %4, [rb];\n\t}"
        :: "r"(dst), "r"(src), "r"(mb), "r"(rank), "r"(bytes) : "memory");
}

__device__ __forceinline__ void mbar_init(unsigned mb, unsigned cnt) {
    asm volatile("mbarrier.init.shared.b64 [%0], %1;" :: "r"(mb), "r"(cnt) : "memory");
}
__device__ __forceinline__ void mbar_arm(unsigned mb, unsigned tx) {
    asm volatile("mbarrier.arrive.expect_tx.shared.b64 _, [%0], %1;"
                 :: "r"(mb), "r"(tx) : "memory");
}
__device__ __forceinline__ void mbar_wait(unsigned mb, unsigned par) {
    unsigned done;
    asm volatile(
        "{\n\t.reg .pred p;\n\t"
        "mbarrier.try_wait.parity.acquire.cluster.shared::cta.b64 p, [%1], %2;\n\t"
        "selp.b32 %0, 1, 0, p;\n\t}"
        : "=r"(done) : "r"(mb), "r"(par) : "memory");
    while (!done) {
        asm volatile(
            "{\n\t.reg .pred p;\n\t"
            "mbarrier.try_wait.parity.acquire.cluster.shared::cta.b64 p, [%1], %2, 0x989680;\n\t"
            "selp.b32 %0, 1, 0, p;\n\t}"
            : "=r"(done) : "r"(mb), "r"(par) : "memory");
    }
}

__device__ __forceinline__ void fence_proxy_async_() {
    asm volatile("fence.proxy.async.shared::cta;" ::: "memory");
}

#define FMA2(acc, w, h) \
    asm("fma.rn.f32x2 %0, %1, %2, %0;" : "+l"(acc) : "l"(w), "l"(h))

__device__ __forceinline__ float lo_f(ull v) {
    return __int_as_float((int)(unsigned)(v & 0xffffffffull));
}
__device__ __forceinline__ float hi_f(ull v) {
    return __int_as_float((int)(unsigned)(v >> 32));
}

// ---------------- embedding (+ progress-counter reset) ----------------
__global__ void embed_kernel(const int* __restrict__ words,
                             const float* __restrict__ emb,
                             float* __restrict__ x) {
    if (blockIdx.x == 0 && threadIdx.x < 32)
        ((volatile int*)g_prog)[threadIdx.x] = 0;
    int i = blockIdx.x * blockDim.x + threadIdx.x;
    if (i < TT * EMBD) {
        int t = i / EMBD, k = i % EMBD;
        x[i] = emb[(size_t)words[t] * EMBD + k];
    }
}

// ---------------- input-projection GEMM (R7 scalar, proven) ----------------
#define BM 128
#define BN 128
#define BK 16

__global__ void __launch_bounds__(256, 2) gemm_gi_kernel(
    const float* __restrict__ A, int M, int K,
    const float* __restrict__ Wf, const float* __restrict__ Wb,
    const float* __restrict__ bihf, const float* __restrict__ bhhf,
    const float* __restrict__ bihb, const float* __restrict__ bhhb,
    float* __restrict__ out)
{
    __shared__ float As[BK][BM + 4];
    __shared__ float Ws[BK][BN + 4];

    const int dir = blockIdx.z;
    const float* W   = dir ? Wb   : Wf;
    const float* bih = dir ? bihb : bihf;
    const float* bhh = dir ? bhhb : bhhf;

    const int n0 = blockIdx.x * BN;
    const int m0 = blockIdx.y * BM;
    const int tid = threadIdx.x;
    const int tx = tid & 15, ty = tid >> 4;

    float acc[8][8];
    #pragma unroll
    for (int i = 0; i < 8; i++)
        #pragma unroll
        for (int j = 0; j < 8; j++) acc[i][j] = 0.f;

    for (int k0 = 0; k0 < K; k0 += BK) {
        #pragma unroll
        for (int e = tid; e < BM * BK; e += 256) {
            int m = e >> 4, k = e & 15;
            int kk = k0 + k;
            As[k][m] = (kk < K) ? A[(size_t)(m0 + m) * K + kk] : 0.f;
        }
        #pragma unroll
        for (int e = tid; e < BN * BK; e += 256) {
            int n = e >> 4, k = e & 15;
            int kk = k0 + k;
            Ws[k][n] = (kk < K) ? W[(size_t)(n0 + n) * K + kk] : 0.f;
        }
        __syncthreads();
        #pragma unroll
        for (int k = 0; k < BK; k++) {
            float a[8], b[8];
            #pragma unroll
            for (int i = 0; i < 8; i++) a[i] = As[k][ty * 8 + i];
            #pragma unroll
            for (int i = 0; i < 8; i++) b[i] = Ws[k][tx * 8 + i];
            #pragma unroll
            for (int i = 0; i < 8; i++)
                #pragma unroll
                for (int j = 0; j < 8; j++)
                    acc[i][j] += a[i] * b[j];
        }
        __syncthreads();
    }

    #pragma unroll
    for (int i = 0; i < 8; i++) {
        int m = m0 + ty * 8 + i;
        #pragma unroll
        for (int j = 0; j < 8; j++) {
            int n = n0 + tx * 8 + j;
            float v = acc[i][j] + bih[n] + (n < 1024 ? bhh[n] : 0.f);
            out[(size_t)dir * M * G3 + (size_t)m * G3 + n] = v;
        }
    }
}

// ---------------- GRU body (R7 reduce-scatter, + gi2, + publish) ----------
__device__ __forceinline__ void gru_body(
    const float* __restrict__ gi, const float* __restrict__ gi2,
    const float* __restrict__ w_hh, const float* __restrict__ b_hh,
    int dir, int crank,
    float* __restrict__ y_out, float* __restrict__ state_out, int publish)
{
    __shared__ __align__(16) float hsl[2][32];
    __shared__ __align__(16) float stage[16][2][96];
    __shared__ __align__(16) float pbuf[2][16][96];
    __shared__ __align__(8) ull mbar[2];

    const int tid  = threadIdx.x;
    const int warp = tid >> 5;
    const int lane = tid & 31;

    const float* gid  = gi + (size_t)dir * TT * G3;
    const float* gid2 = gi2 ? gi2 + (size_t)dir * TT * G3 : nullptr;

    const int jd = 32 * warp + lane;
    const int jo = 32 * crank + lane;

    ull w[48];
    #pragma unroll
    for (int g = 0; g < 3; g++) {
        const float* base = w_hh + (size_t)(g * HIDN + jd) * HIDN + 32 * crank;
        #pragma unroll
        for (int p = 0; p < 16; p++)
            w[g * 16 + p] = *(const ull*)(base + 2 * p);
    }

    if (tid < 32) { hsl[0][tid] = 0.f; hsl[1][tid] = 0.f; }
    const float bhn = (warp == 0) ? b_hh[1024 + jo] : 0.f;

    const unsigned stgb = (unsigned)__cvta_generic_to_shared(stage);
    const unsigned pbb  = (unsigned)__cvta_generic_to_shared(pbuf);
    const unsigned mbb  = (unsigned)__cvta_generic_to_shared(mbar);
    const unsigned TXB  = 16u * 384u;

    if (tid == 0) {
        mbar_init(mbb, 1);
        mbar_init(mbb + 8, 1);
        mbar_arm(mbb, TXB);
        mbar_arm(mbb + 8, TXB);
    }

    const int t0    = dir ? TT - 1 : 0;
    const int gstep = dir ? -G3 : G3;
    const float* gp  = gid + (size_t)t0 * G3 + jo;
    const float* gp2 = gid2 ? gid2 + (size_t)t0 * G3 + jo : nullptr;
    float gr = 0.f, gz = 0.f, gn = 0.f;
    if (warp == 0) {
        gr = gp[0]; gz = gp[512]; gn = gp[1024];
        if (gp2) { gr += gp2[0]; gz += gp2[512]; gn += gp2[1024]; }
    }

    float* yp = y_out + (size_t)t0 * 1024 + dir * 512 + jo;
    const int ystep = dir ? -1024 : 1024;

    __syncthreads();
    cluster_sync_();

    for (int s = 0; s < TT; s++) {
        const int b = s & 1;

        // phase 1: whole-row partials over local h slice
        ull a0 = 0, a1 = 0, a2 = 0;
        const ull* h2 = (const ull*)hsl[b];
        #pragma unroll
        for (int p = 0; p < 16; p++) {
            ull hv = h2[p];
            FMA2(a0, w[p],      hv);
            FMA2(a1, w[16 + p], hv);
            FMA2(a2, w[32 + p], hv);
        }

        float ngr = 0.f, ngz = 0.f, ngn = 0.f;
        if (warp == 0 && s + 1 < TT) {
            const float* g2 = gp + gstep;
            ngr = g2[0]; ngz = g2[512]; ngn = g2[1024];
            if (gp2) {
                const float* g3 = gp2 + gstep;
                ngr += g3[0]; ngz += g3[512]; ngn += g3[1024];
            }
        }

        // phase 2: stage + one bulk per warp to dest CTA = warp
        {
            float* st = &stage[warp][b][3 * lane];
            st[0] = lo_f(a0) + hi_f(a0);
            st[1] = lo_f(a1) + hi_f(a1);
            st[2] = lo_f(a2) + hi_f(a2);
        }
        __syncwarp();
        if (lane == 0) {
            fence_proxy_async_();
            bulk_push(pbb + (unsigned)((b * 16 + crank) * 384),
                      stgb + (unsigned)((warp * 2 + b) * 384),
                      mbb + (unsigned)(b * 8),
                      (unsigned)warp, 384u);
        }

        // phase 3: warp0 reduces + gates
        if (warp == 0) {
            mbar_wait(mbb + (unsigned)(b * 8), ((unsigned)s >> 1) & 1u);
            if (lane == 0) mbar_arm(mbb + (unsigned)(b * 8), TXB);

            float sr = 0.f, sz = 0.f, sn = 0.f;
            const float* pb = &pbuf[b][0][3 * lane];
            #pragma unroll
            for (int src = 0; src < 16; src++) {
                const float* r = pb + src * 96;
                sr += r[0]; sz += r[1]; sn += r[2];
            }

            const float hprev = hsl[b][lane];
            float rg = 1.f / (1.f + __expf(-(gr + sr)));
            float zg = 1.f / (1.f + __expf(-(gz + sz)));
            float u  = gn + rg * (sn + bhn);
            float e2 = __expf(2.f * u);
            float ng = 1.f - 2.f / (e2 + 1.f);
            float hnew = ng + zg * (hprev - ng);

            hsl[b ^ 1][lane] = hnew;
            *yp = hnew;
            if (s == TT - 1) state_out[dir * 512 + jo] = hnew;

            gr = ngr; gz = ngz; gn = ngn;

            if (publish && lane == 0 && ((s & 255) == 255)) {
                __threadfence();
                *((volatile int*)&g_prog[dir][crank]) = s + 1;
            }
        }
        gp += gstep; yp += ystep;
        if (gp2) gp2 += gstep;

        __syncthreads();
    }

    cluster_sync_();
}

// ---------------- L1-GEMM worker (runs inside fused kernel) ----------------
// 96 worker CTAs × 16 tiles. Tile g: rank r = g/24 gives (half, t-chunk) in
// readiness order (ready when prog >= 128*(r/2+1)); sub = g%24 -> (dir, ntile).
__device__ void worker_body(
    const float* __restrict__ y0,
    const float* __restrict__ w1f, const float* __restrict__ w1b,
    const float* __restrict__ bif, const float* __restrict__ bhf1,
    const float* __restrict__ bib, const float* __restrict__ bhb1,
    float* __restrict__ gia, float* __restrict__ gib, int wcta)
{
    __shared__ __align__(16) float As[BK][BM + 4];
    __shared__ __align__(16) float Bs[BK][BN + 4];
    __shared__ int wflag;

    const int tid = threadIdx.x;
    const int tx = tid & 15;       // 8 output cols each
    const int ty = tid >> 4;       // 0..31, 4 output rows each
    const int mf = tid >> 2;       // fill row 0..127
    const int kq = (tid & 3) * 4;  // fill k quad

    for (int it = 0; it < 16; it++) {
        const int g   = wcta + 96 * it;       // 0..1535
        const int r   = g / 24, sub = g % 24;
        const int d   = sub / 12, nt = sub % 12;
        const int half = r & 1, q = r >> 1;
        const int tc  = half ? (31 - q) : q;
        const int sreq = 128 * (q + 1);

        // spin until source half of y0 is complete for this t-chunk
        for (;;) {
            if (tid == 0) {
                volatile const int* pr = (volatile const int*)&g_prog[half][0];
                int mn = 1 << 30;
                #pragma unroll
                for (int c = 0; c < 16; c++) { int v = pr[c]; if (v < mn) mn = v; }
                wflag = (mn >= sreq);
                if (!wflag) __nanosleep(2000);
            }
            __syncthreads();
            int ok = wflag;
            __syncthreads();
            if (ok) break;
        }

        const float* W1 = d ? w1b : w1f;
        const int t0 = tc * 128, n0 = nt * 128, koff = half * 512;

        float acc[4][8];
        #pragma unroll
        for (int i = 0; i < 4; i++)
            #pragma unroll
            for (int j = 0; j < 8; j++) acc[i][j] = 0.f;

        for (int k0 = 0; k0 < 512; k0 += BK) {
            float4 va = *(const float4*)&y0[(size_t)(t0 + mf) * 1024 + koff + k0 + kq];
            As[kq + 0][mf] = va.x; As[kq + 1][mf] = va.y;
            As[kq + 2][mf] = va.z; As[kq + 3][mf] = va.w;
            float4 vb = *(const float4*)&W1[(size_t)(n0 + mf) * 1024 + koff + k0 + kq];
            Bs[kq + 0][mf] = vb.x; Bs[kq + 1][mf] = vb.y;
            Bs[kq + 2][mf] = vb.z; Bs[kq + 3][mf] = vb.w;
            __syncthreads();
            #pragma unroll
            for (int k = 0; k < BK; k++) {
                float4 a  = *(const float4*)&As[k][ty * 4];
                float4 b0 = *(const float4*)&Bs[k][tx * 8];
                float4 b1 = *(const float4*)&Bs[k][tx * 8 + 4];
                float av[4] = {a.x, a.y, a.z, a.w};
                float bv[8] = {b0.x, b0.y, b0.z, b0.w, b1.x, b1.y, b1.z, b1.w};
                #pragma unroll
                for (int i = 0; i < 4; i++)
                    #pragma unroll
                    for (int j = 0; j < 8; j++)
                        acc[i][j] += av[i] * bv[j];
            }
            __syncthreads();
        }

        #pragma unroll
        for (int i = 0; i < 4; i++) {
            const int t = t0 + ty * 4 + i;
            #pragma unroll
            for (int j = 0; j < 8; j++) {
                const int n = n0 + tx * 8 + j;
                const size_t o = ((size_t)d * TT + t) * G3 + n;
                if (half == 0) {
                    float bias = (d ? bib[n] : bif[n]) +
                                 (n < 1024 ? (d ? bhb1[n] : bhf1[n]) : 0.f);
                    gia[o] = acc[i][j] + bias;
                } else {
                    gib[o] = acc[i][j];
                }
            }
        }
    }
}

// ---------------- fused L0-GRU + L1-GEMM kernel ----------------
__global__ void __launch_bounds__(512, 1) fused_l0_kernel(
    const float* __restrict__ gi0,
    const float* __restrict__ wh0f, const float* __restrict__ wh0b,
    const float* __restrict__ bh0f, const float* __restrict__ bh0b,
    float* __restrict__ y0, float* __restrict__ state_out,
    const float* __restrict__ w1f, const float* __restrict__ w1b,
    const float* __restrict__ bif, const float* __restrict__ bhf1,
    const float* __restrict__ bib, const float* __restrict__ bhb1,
    float* __restrict__ gia, float* __restrict__ gib)
{
    if (blockIdx.x < 32) {
        const int crank = blockIdx.x & 15;
        const int dir   = blockIdx.x >> 4;
        gru_body(gi0, nullptr, dir ? wh0b : wh0f, dir ? bh0b : bh0f,
                 dir, crank, y0, state_out, 1);
    } else {
        worker_body(y0, w1f, w1b, bif, bhf1, bib, bhb1, gia, gib,
                    (int)blockIdx.x - 32);
    }
}

// ---------------- standalone L1 GRU kernel ----------------
__global__ void __launch_bounds__(512, 1) gru_l1_kernel(
    const float* __restrict__ gia, const float* __restrict__ gib,
    const float* __restrict__ whf, const float* __restrict__ whb,
    const float* __restrict__ bhf, const float* __restrict__ bhb,
    float* __restrict__ y_out, float* __restrict__ state_out)
{
    const int crank = blockIdx.x & 15;
    const int dir   = blockIdx.x >> 4;
    gru_body(gia, gib, dir ? whb : whf, dir ? bhb : bhf,
             dir, crank, y_out, state_out, 0);
}

// ---------------- launch ----------------
extern "C" void kernel_launch(void* const* d_in, const int* in_sizes, int n_in,
                              void* d_out, int out_size) {
    const int*   words    = (const int*)d_in[0];
    const float* emb      = (const float*)d_in[1];
    const float* w_ih_l0f = (const float*)d_in[2];
    const float* w_hh_l0f = (const float*)d_in[3];
    const float* b_ih_l0f = (const float*)d_in[4];
    const float* b_hh_l0f = (const float*)d_in[5];
    const float* w_ih_l0b = (const float*)d_in[6];
    const float* w_hh_l0b = (const float*)d_in[7];
    const float* b_ih_l0b = (const float*)d_in[8];
    const float* b_hh_l0b = (const float*)d_in[9];
    const float* w_ih_l1f = (const float*)d_in[10];
    const float* w_hh_l1f = (const float*)d_in[11];
    const float* b_ih_l1f = (const float*)d_in[12];
    const float* b_hh_l1f = (const float*)d_in[13];
    const float* w_ih_l1b = (const float*)d_in[14];
    const float* w_hh_l1b = (const float*)d_in[15];
    const float* b_ih_l1b = (const float*)d_in[16];
    const float* b_hh_l1b = (const float*)d_in[17];
    float* out = (float*)d_out;

    float *px, *py0, *pgi0, *pgi1, *pgi1b;
    cudaGetSymbolAddress((void**)&px,    g_x);
    cudaGetSymbolAddress((void**)&py0,   g_y0);
    cudaGetSymbolAddress((void**)&pgi0,  g_gi0);
    cudaGetSymbolAddress((void**)&pgi1,  g_gi1);
    cudaGetSymbolAddress((void**)&pgi1b, g_gi1b);

    // 1) embedding + progress reset
    embed_kernel<<<(TT * EMBD + 255) / 256, 256>>>(words, emb, px);

    // 2) layer-0 input projections (both directions)
    dim3 gg(G3 / BN, TT / BM, 2);
    gemm_gi_kernel<<<gg, 256>>>(px, TT, EMBD,
                                w_ih_l0f, w_ih_l0b,
                                b_ih_l0f, b_hh_l0f, b_ih_l0b, b_hh_l0b, pgi0);

    // 3) fused: layer-0 recurrence + layer-1 input projections (overlapped)
    {
        cudaFuncSetAttribute(fused_l0_kernel,
                             cudaFuncAttributeNonPortableClusterSizeAllowed, 1);
        cudaLaunchConfig_t cfg = {};
        cfg.gridDim = dim3(128, 1, 1);
        cfg.blockDim = dim3(512, 1, 1);
        cfg.dynamicSmemBytes = 0;
        cfg.stream = 0;
        cudaLaunchAttribute attr[1];
        attr[0].id = cudaLaunchAttributeClusterDimension;
        attr[0].val.clusterDim.x = 16;
        attr[0].val.clusterDim.y = 1;
        attr[0].val.clusterDim.z = 1;
        cfg.attrs = attr;
        cfg.numAttrs = 1;
        cudaLaunchKernelEx(&cfg, fused_l0_kernel,
                           (const float*)pgi0, w_hh_l0f, w_hh_l0b,
                           b_hh_l0f, b_hh_l0b,
                           py0, out + (size_t)TT * 1024,
                           w_ih_l1f, w_ih_l1b,
                           b_ih_l1f, b_hh_l1f, b_ih_l1b, b_hh_l1b,
                           pgi1, pgi1b);
    }

    // 4) layer-1 recurrence
    {
        cudaFuncSetAttribute(gru_l1_kernel,
                             cudaFuncAttributeNonPortableClusterSizeAllowed, 1);
        cudaLaunchConfig_t cfg = {};
        cfg.gridDim = dim3(32, 1, 1);
        cfg.blockDim = dim3(512, 1, 1);
        cfg.dynamicSmemBytes = 0;
        cfg.stream = 0;
        cudaLaunchAttribute attr[1];
        attr[0].id = cudaLaunchAttributeClusterDimension;
        attr[0].val.clusterDim.x = 16;
        attr[0].val.clusterDim.y = 1;
        attr[0].val.clusterDim.z = 1;
        cfg.attrs = attr;
        cfg.numAttrs = 1;
        cudaLaunchKernelEx(&cfg, gru_l1_kernel,
                           (const float*)pgi1, (const float*)pgi1b,
                           w_hh_l1f, w_hh_l1b, b_hh_l1f, b_hh_l1b,
                           out, out + (size_t)TT * 1024 + 1024);
    }
}

// round 14
// speedup vs baseline: 1.1416x; 1.1416x over previous
#include <cuda_runtime.h>
#include <cstdint>
#include <cstddef>

#define TT   4096
#define EMBD 100
#define HIDN 512
#define G3   1536

typedef unsigned long long ull;

// ---------------- scratch (no cudaMalloc allowed) ----------------
__device__ float g_x[TT * EMBD];            // embedded inputs      (1.6 MB)
__device__ float g_y0[TT * 1024];           // layer-0 output       (16.8 MB)
__device__ float g_gi0[2 * TT * G3];        // layer-0 input gates  (50.3 MB)
__device__ float g_gi1[2 * TT * G3];        // layer-1 input gates  (50.3 MB)

// ---------------- helpers ----------------
__device__ __forceinline__ void cluster_sync_() {
    asm volatile("barrier.cluster.arrive.aligned;" ::: "memory");
    asm volatile("barrier.cluster.wait.aligned;" ::: "memory");
}

// 384B bulk push: local smem stage -> peer CTA's smem, complete_tx on peer mbar
__device__ __forceinline__ void bulk_push(unsigned dst, unsigned src,
                                          unsigned mb, unsigned rank,
                                          unsigned bytes) {
    asm volatile(
        "{\n\t.reg .u32 rd, rb;\n\t"
        "mapa.shared::cluster.u32 rd, %0, %3;\n\t"
        "mapa.shared::cluster.u32 rb, %2, %3;\n\t"
        "cp.async.bulk.shared::cluster.shared::cta.mbarrier::complete_tx::bytes "
        "[rd], [%1], %4, [rb];\n\t}"
        :: "r"(dst), "r"(src), "r"(mb), "r"(rank), "r"(bytes) : "memory");
}

__device__ __forceinline__ void mbar_init(unsigned mb, unsigned cnt) {
    asm volatile("mbarrier.init.shared.b64 [%0], %1;" :: "r"(mb), "r"(cnt) : "memory");
}
__device__ __forceinline__ void mbar_arm(unsigned mb, unsigned tx) {
    asm volatile("mbarrier.arrive.expect_tx.shared.b64 _, [%0], %1;"
                 :: "r"(mb), "r"(tx) : "memory");
}
__device__ __forceinline__ void mbar_wait(unsigned mb, unsigned par) {
    unsigned done;
    asm volatile(
        "{\n\t.reg .pred p;\n\t"
        "mbarrier.try_wait.parity.acquire.cluster.shared::cta.b64 p, [%1], %2;\n\t"
        "selp.b32 %0, 1, 0, p;\n\t}"
        : "=r"(done) : "r"(mb), "r"(par) : "memory");
    while (!done) {
        asm volatile(
            "{\n\t.reg .pred p;\n\t"
            "mbarrier.try_wait.parity.acquire.cluster.shared::cta.b64 p, [%1], %2, 0x989680;\n\t"
            "selp.b32 %0, 1, 0, p;\n\t}"
            : "=r"(done) : "r"(mb), "r"(par) : "memory");
    }
}

__device__ __forceinline__ void fence_proxy_async_() {
    asm volatile("fence.proxy.async.shared::cta;" ::: "memory");
}

// packed f32x2 ops
#define FMA2(acc, w, h) \
    asm("fma.rn.f32x2 %0, %1, %2, %0;" : "+l"(acc) : "l"(w), "l"(h))
#define ADD2(acc, v) \
    asm("add.rn.f32x2 %0, %0, %1;" : "+l"(acc) : "l"(v))

__device__ __forceinline__ float lo_f(ull v) {
    return __int_as_float((int)(unsigned)(v & 0xffffffffull));
}
__device__ __forceinline__ float hi_f(ull v) {
    return __int_as_float((int)(unsigned)(v >> 32));
}
__device__ __forceinline__ ull pack2(float lo, float hi) {
    return ((ull)__float_as_uint(hi) << 32) | (ull)__float_as_uint(lo);
}

// ---------------- embedding ----------------
__global__ void embed_kernel(const int* __restrict__ words,
                             const float* __restrict__ emb,
                             float* __restrict__ x) {
    int i = blockIdx.x * blockDim.x + threadIdx.x;
    if (i < TT * EMBD) {
        int t = i / EMBD, k = i % EMBD;
        x[i] = emb[(size_t)words[t] * EMBD + k];
    }
}

// ---------------- input-projection GEMM (R7 scalar, proven) ----------------
#define BM 128
#define BN 128
#define BK 16

__global__ void __launch_bounds__(256, 2) gemm_gi_kernel(
    const float* __restrict__ A, int M, int K,
    const float* __restrict__ Wf, const float* __restrict__ Wb,
    const float* __restrict__ bihf, const float* __restrict__ bhhf,
    const float* __restrict__ bihb, const float* __restrict__ bhhb,
    float* __restrict__ out)
{
    __shared__ float As[BK][BM + 4];
    __shared__ float Ws[BK][BN + 4];

    const int dir = blockIdx.z;
    const float* W   = dir ? Wb   : Wf;
    const float* bih = dir ? bihb : bihf;
    const float* bhh = dir ? bhhb : bhhf;

    const int n0 = blockIdx.x * BN;
    const int m0 = blockIdx.y * BM;
    const int tid = threadIdx.x;
    const int tx = tid & 15, ty = tid >> 4;

    float acc[8][8];
    #pragma unroll
    for (int i = 0; i < 8; i++)
        #pragma unroll
        for (int j = 0; j < 8; j++) acc[i][j] = 0.f;

    for (int k0 = 0; k0 < K; k0 += BK) {
        #pragma unroll
        for (int e = tid; e < BM * BK; e += 256) {
            int m = e >> 4, k = e & 15;
            int kk = k0 + k;
            As[k][m] = (kk < K) ? A[(size_t)(m0 + m) * K + kk] : 0.f;
        }
        #pragma unroll
        for (int e = tid; e < BN * BK; e += 256) {
            int n = e >> 4, k = e & 15;
            int kk = k0 + k;
            Ws[k][n] = (kk < K) ? W[(size_t)(n0 + n) * K + kk] : 0.f;
        }
        __syncthreads();
        #pragma unroll
        for (int k = 0; k < BK; k++) {
            float a[8], b[8];
            #pragma unroll
            for (int i = 0; i < 8; i++) a[i] = As[k][ty * 8 + i];
            #pragma unroll
            for (int i = 0; i < 8; i++) b[i] = Ws[k][tx * 8 + i];
            #pragma unroll
            for (int i = 0; i < 8; i++)
                #pragma unroll
                for (int j = 0; j < 8; j++)
                    acc[i][j] += a[i] * b[j];
        }
        __syncthreads();
    }

    #pragma unroll
    for (int i = 0; i < 8; i++) {
        int m = m0 + ty * 8 + i;
        #pragma unroll
        for (int j = 0; j < 8; j++) {
            int n = n0 + tx * 8 + j;
            float v = acc[i][j] + bih[n] + (n < 1024 ? bhh[n] : 0.f);
            out[(size_t)dir * M * G3 + (size_t)m * G3 + n] = v;
        }
    }
}

// ---------------- recurrent layer: reduce-scatter scheme (R7 + packed) ----
// 32 CTAs = 2 clusters of 16 (fwd/bwd). CTA c owns h-slice k=[32c,32c+32).
// Stage/pbuf layout per (warp|src, buf): [32 x u64 (r,z)] [32 x f32 (n)].
// Per step:
//   phase1: 8x LDS.128 h + 48 fma.rn.f32x2 (whole rows, no shuffle reduce)
//   phase2: STS.64 + STS.32 stage, syncwarp, lane0 fence + ONE bulk to dest w
//   phase3 (warp0): mbar wait -> 16 LDS.64 + add.rn.f32x2 (4 ILP chains) for
//     r,z + 16 LDS.32 + 4-chain FADD for n -> gates -> h slice + y_out
//   phase4: __syncthreads
__global__ void __launch_bounds__(512, 1) gru_layer_kernel(
    const float* __restrict__ gi,                 // [2][T][1536]
    const float* __restrict__ whf, const float* __restrict__ whb,
    const float* __restrict__ bhf, const float* __restrict__ bhb,
    float* __restrict__ y_out,                    // [T][1024]
    float* __restrict__ state_out)                // [2][512]
{
    __shared__ __align__(16) float hsl[2][32];            // local h slice x2
    __shared__ __align__(16) float stage[16][2][96];      // per-warp out, x2
    __shared__ __align__(16) float pbuf[2][16][96];       // incoming partials
    __shared__ __align__(8) ull mbar[2];

    const int crank = blockIdx.x & 15;
    const int dir   = blockIdx.x >> 4;
    const int tid   = threadIdx.x;
    const int warp  = tid >> 5;
    const int lane  = tid & 31;

    const float* w_hh = dir ? whb : whf;
    const float* b_hh = dir ? bhb : bhf;
    const float* gid  = gi + (size_t)dir * TT * G3;

    const int jd = 32 * warp + lane;      // output whose partials we compute
    const int jo = 32 * crank + lane;     // own output (warp0 gate duty)

    // ---- weights: rows (g, jd) over k in [32*crank, 32*crank+32) ----
    ull w[48];
    #pragma unroll
    for (int g = 0; g < 3; g++) {
        const float* base = w_hh + (size_t)(g * HIDN + jd) * HIDN + 32 * crank;
        #pragma unroll
        for (int p = 0; p < 16; p++)
            w[g * 16 + p] = *(const ull*)(base + 2 * p);
    }

    if (tid < 32) { hsl[0][tid] = 0.f; hsl[1][tid] = 0.f; }
    const float bhn = (warp == 0) ? b_hh[1024 + jo] : 0.f;

    const unsigned stgb = (unsigned)__cvta_generic_to_shared(stage);
    const unsigned pbb  = (unsigned)__cvta_generic_to_shared(pbuf);
    const unsigned mbb  = (unsigned)__cvta_generic_to_shared(mbar);
    const unsigned TXB  = 16u * 384u;

    if (tid == 0) {
        mbar_init(mbb, 1);
        mbar_init(mbb + 8, 1);
        mbar_arm(mbb, TXB);          // step 0 bulks
        mbar_arm(mbb + 8, TXB);      // step 1 bulks
    }

    // gi walk (warp0 lanes gate their own outputs)
    const int t0    = dir ? TT - 1 : 0;
    const int gstep = dir ? -G3 : G3;
    const float* gp = gid + (size_t)t0 * G3 + jo;
    float gr = 0.f, gz = 0.f, gn = 0.f;
    if (warp == 0) { gr = gp[0]; gz = gp[512]; gn = gp[1024]; }

    float* yp = y_out + (size_t)t0 * 1024 + dir * 512 + jo;
    const int ystep = dir ? -1024 : 1024;

    __syncthreads();
    cluster_sync_();    // mbarriers + h zeros visible cluster-wide

    for (int s = 0; s < TT; s++) {
        const int b = s & 1;

        // ---- phase 1: whole-row partials over the local h slice ----
        ull a0 = 0, a1 = 0, a2 = 0;
        const ulonglong2* h4 = (const ulonglong2*)hsl[b];
        #pragma unroll
        for (int p = 0; p < 8; p++) {
            ulonglong2 hv = h4[p];
            FMA2(a0, w[2 * p],          hv.x);
            FMA2(a0, w[2 * p + 1],      hv.y);
            FMA2(a1, w[16 + 2 * p],     hv.x);
            FMA2(a1, w[16 + 2 * p + 1], hv.y);
            FMA2(a2, w[32 + 2 * p],     hv.x);
            FMA2(a2, w[32 + 2 * p + 1], hv.y);
        }

        // warp0: prefetch gi for step s+1 (consumed next iter, fully hidden)
        float ngr = 0.f, ngz = 0.f, ngn = 0.f;
        if (warp == 0 && s + 1 < TT) {
            const float* g2 = gp + gstep;
            ngr = g2[0]; ngz = g2[512]; ngn = g2[1024];
        }

        // ---- phase 2: packed stage; one bulk per warp to dest CTA = warp ----
        {
            float sr = lo_f(a0) + hi_f(a0);
            float sz = lo_f(a1) + hi_f(a1);
            float sn = lo_f(a2) + hi_f(a2);
            ((ull*)&stage[warp][b][0])[lane] = pack2(sr, sz);
            stage[warp][b][64 + lane] = sn;
        }
        __syncwarp();
        if (lane == 0) {
            fence_proxy_async_();
            bulk_push(pbb + (unsigned)((b * 16 + crank) * 384),
                      stgb + (unsigned)((warp * 2 + b) * 384),
                      mbb + (unsigned)(b * 8),
                      (unsigned)warp, 384u);
        }

        // ---- phase 3: warp0 packed ILP reduce + gates ----
        if (warp == 0) {
            mbar_wait(mbb + (unsigned)(b * 8), ((unsigned)s >> 1) & 1u);
            if (lane == 0) mbar_arm(mbb + (unsigned)(b * 8), TXB);  // for s+2

            const ull* pu = (const ull*)&pbuf[b][0][0];   // src stride 48 ull
            const float* pn = &pbuf[b][0][64];            // src stride 96 f32
            ull c0 = 0, c1 = 0, c2 = 0, c3 = 0;
            float f0 = 0.f, f1 = 0.f, f2 = 0.f, f3 = 0.f;
            #pragma unroll
            for (int q = 0; q < 4; q++) {
                ADD2(c0, pu[(4 * q + 0) * 48 + lane]);
                ADD2(c1, pu[(4 * q + 1) * 48 + lane]);
                ADD2(c2, pu[(4 * q + 2) * 48 + lane]);
                ADD2(c3, pu[(4 * q + 3) * 48 + lane]);
                f0 += pn[(4 * q + 0) * 96 + lane];
                f1 += pn[(4 * q + 1) * 96 + lane];
                f2 += pn[(4 * q + 2) * 96 + lane];
                f3 += pn[(4 * q + 3) * 96 + lane];
            }
            ADD2(c0, c1); ADD2(c2, c3); ADD2(c0, c2);
            const float sr = lo_f(c0);
            const float sz = hi_f(c0);
            const float sn = (f0 + f1) + (f2 + f3);

            const float hprev = hsl[b][lane];
            float rg = 1.f / (1.f + __expf(-(gr + sr)));
            float zg = 1.f / (1.f + __expf(-(gz + sz)));
            float u  = gn + rg * (sn + bhn);
            float e2 = __expf(2.f * u);
            float ng = 1.f - 2.f / (e2 + 1.f);       // tanh(u), inf-safe
            float hnew = ng + zg * (hprev - ng);

            hsl[b ^ 1][lane] = hnew;
            *yp = hnew;
            if (s == TT - 1) state_out[dir * 512 + jo] = hnew;

            gr = ngr; gz = ngz; gn = ngn;
        }
        gp += gstep; yp += ystep;

        __syncthreads();    // h slice published; stage/pbuf reuse safe by
                            // the transitive wait-chain argument
    }

    cluster_sync_();    // keep smem alive until all in-flight bulks landed
}

// ---------------- launch ----------------
static void launch_gru(const float* gi,
                       const float* whf, const float* whb,
                       const float* bhf, const float* bhb,
                       float* y_out, float* state_out) {
    cudaFuncSetAttribute(gru_layer_kernel,
                         cudaFuncAttributeNonPortableClusterSizeAllowed, 1);

    cudaLaunchConfig_t cfg = {};
    cfg.gridDim = dim3(32, 1, 1);
    cfg.blockDim = dim3(512, 1, 1);
    cfg.dynamicSmemBytes = 0;
    cfg.stream = 0;
    cudaLaunchAttribute attr[1];
    attr[0].id = cudaLaunchAttributeClusterDimension;
    attr[0].val.clusterDim.x = 16;
    attr[0].val.clusterDim.y = 1;
    attr[0].val.clusterDim.z = 1;
    cfg.attrs = attr;
    cfg.numAttrs = 1;

    cudaLaunchKernelEx(&cfg, gru_layer_kernel, gi, whf, whb, bhf, bhb, y_out, state_out);
}

extern "C" void kernel_launch(void* const* d_in, const int* in_sizes, int n_in,
                              void* d_out, int out_size) {
    const int*   words    = (const int*)d_in[0];
    const float* emb      = (const float*)d_in[1];
    const float* w_ih_l0f = (const float*)d_in[2];
    const float* w_hh_l0f = (const float*)d_in[3];
    const float* b_ih_l0f = (const float*)d_in[4];
    const float* b_hh_l0f = (const float*)d_in[5];
    const float* w_ih_l0b = (const float*)d_in[6];
    const float* w_hh_l0b = (const float*)d_in[7];
    const float* b_ih_l0b = (const float*)d_in[8];
    const float* b_hh_l0b = (const float*)d_in[9];
    const float* w_ih_l1f = (const float*)d_in[10];
    const float* w_hh_l1f = (const float*)d_in[11];
    const float* b_ih_l1f = (const float*)d_in[12];
    const float* b_hh_l1f = (const float*)d_in[13];
    const float* w_ih_l1b = (const float*)d_in[14];
    const float* w_hh_l1b = (const float*)d_in[15];
    const float* b_ih_l1b = (const float*)d_in[16];
    const float* b_hh_l1b = (const float*)d_in[17];
    float* out = (float*)d_out;

    float *px, *py0, *pgi0, *pgi1;
    cudaGetSymbolAddress((void**)&px,   g_x);
    cudaGetSymbolAddress((void**)&py0,  g_y0);
    cudaGetSymbolAddress((void**)&pgi0, g_gi0);
    cudaGetSymbolAddress((void**)&pgi1, g_gi1);

    // 1) embedding
    embed_kernel<<<(TT * EMBD + 255) / 256, 256>>>(words, emb, px);

    // 2) layer-0 input projections (both directions)
    dim3 gg(G3 / BN, TT / BM, 2);
    gemm_gi_kernel<<<gg, 256>>>(px, TT, EMBD,
                                w_ih_l0f, w_ih_l0b,
                                b_ih_l0f, b_hh_l0f, b_ih_l0b, b_hh_l0b, pgi0);

    // 3) layer-0 recurrence
    launch_gru(pgi0, w_hh_l0f, w_hh_l0b, b_hh_l0f, b_hh_l0b,
               py0, out + (size_t)TT * 1024);

    // 4) layer-1 input projections
    gemm_gi_kernel<<<gg, 256>>>(py0, TT, 1024,
                                w_ih_l1f, w_ih_l1b,
                                b_ih_l1f, b_hh_l1f, b_ih_l1b, b_hh_l1b, pgi1);

    // 5) layer-1 recurrence
    launch_gru(pgi1, w_hh_l1f, w_hh_l1b, b_hh_l1f, b_hh_l1b,
               out, out + (size_t)TT * 1024 + 1024);
}